// round 12
// baseline (speedup 1.0000x reference)
#include <cuda_runtime.h>
#include <cstdint>

#define VSIZE 100000
#define EDIM  128
#define DA    60
#define DAP   64            // padded projection row (256B aligned)
#define BN    4096
#define TN    8
#define CN    200
#define EPSV  1e-6f
#define CCH   100

typedef unsigned long long ull;

// Scratch (device globals: no allocation allowed)
__device__ float g_cprojn[(size_t)VSIZE * DAP];    // normalized c projections [V,64p]
__device__ float g_tprojn[(size_t)BN * TN * DAP];  // normalized t projections [B*T,64p]
__device__ float g_Mt[EDIM * EDIM];                // Mt[k][e] = (R_w @ Bc_w)[e][k]
__device__ float g_bias2[EDIM];                    // R_w @ Bc_b + R_b
__device__ float g_S[(size_t)BN * TN * EDIM];      // attn @ u   [B*T,128]

// ---------------------------------------------------------------------------
// packed fp32x2 helpers
// ---------------------------------------------------------------------------
__device__ __forceinline__ ull ffma2(ull a, ull b, ull c) {
    ull d; asm("fma.rn.f32x2 %0,%1,%2,%3;" : "=l"(d) : "l"(a), "l"(b), "l"(c));
    return d;
}
__device__ __forceinline__ ull add2(ull a, ull b) {
    ull d; asm("add.rn.f32x2 %0,%1,%2;" : "=l"(d) : "l"(a), "l"(b));
    return d;
}
__device__ __forceinline__ ull dup2(float x) {
    ull r; asm("mov.b64 %0,{%1,%1};" : "=l"(r) : "f"(x)); return r;
}
__device__ __forceinline__ float2 upk(ull v) {
    float a, b; asm("mov.b64 {%0,%1},%2;" : "=f"(a), "=f"(b) : "l"(v));
    return make_float2(a, b);
}

// ---------------------------------------------------------------------------
// Kernel 0: fuse M = R_w @ Bc_w (stored transposed) and bias2 = R_w@Bc_b + R_b
// ---------------------------------------------------------------------------
__global__ void fuse_kernel(const float* __restrict__ Rw, const float* __restrict__ Bw,
                            const float* __restrict__ Bb, const float* __restrict__ Rb)
{
    int e = blockIdx.x;
    int k = threadIdx.x;
    __shared__ float sR[EDIM];
    __shared__ float sP[EDIM];
    sR[k] = Rw[e * EDIM + k];
    __syncthreads();
    float acc = 0.f;
#pragma unroll 8
    for (int j = 0; j < EDIM; j++)
        acc = fmaf(sR[j], Bw[j * EDIM + k], acc);
    g_Mt[k * EDIM + e] = acc;
    sP[k] = sR[k] * Bb[k];
    __syncthreads();
    if (k == 0) {
        float s = 0.f;
        for (int j = 0; j < EDIM; j++) s += sP[j];
        g_bias2[e] = s + Rb[e];
    }
}

// ---------------------------------------------------------------------------
// Kernel 1/2: project 128 rows/CTA through W[60,128]+bias, eps-clamped L2 norm.
// Micro-tile 4r x 8d. k split in 4 quarters of 32 -> static smem 40KB
// (sWt[32][64]=8K + union(sX,sOut)[128][64]=32K), safely under the limit.
// Writes PADDED global rows (DAP=64 floats; cols 60..63 = 0).
// ---------------------------------------------------------------------------
template <bool GATHER>
__global__ __launch_bounds__(256)
void proj_kernel(const float* __restrict__ table,
                 const float* __restrict__ W,
                 const float* __restrict__ bias,
                 const int* __restrict__ idx)
{
    __shared__ __align__(16) float sWt[32][64];         // 8 KB (k-quarter x d)
    __shared__ __align__(16) char  arena[128 * 64 * 4]; // 32 KB: sX then sOut
    float (*sX)[64]   = (float(*)[64])arena;
    float (*sOut)[64] = (float(*)[64])arena;

    int tid = threadIdx.x;
    int rg = tid >> 3, dg = tid & 7;          // rows 4rg..4rg+3, d-cols 4dg / 32+4dg
    long base = (long)blockIdx.x * 128;

    ull aA[4][2], aB[4][2];
#pragma unroll
    for (int j = 0; j < 4; j++) { aA[j][0] = aA[j][1] = aB[j][0] = aB[j][1] = 0; }

#pragma unroll
    for (int h = 0; h < 4; h++) {
        __syncthreads();
        // stage W quarter transposed, d-consecutive (conflict-free STS; W is L2-hot)
        for (int i = tid; i < 32 * 64; i += 256) {
            int kk = i >> 6, d = i & 63;
            sWt[kk][d] = (d < DA) ? W[d * EDIM + 32 * h + kk] : 0.f;
        }
        // stage x quarter: 128 rows x 32 floats (8 float4 per row)
        for (int i = tid; i < 128 * 8; i += 256) {
            int r = i >> 3, q = i & 7;
            long gr = base + r;
            long rv;
            if (GATHER) rv = (long)idx[gr];
            else        rv = (gr < VSIZE) ? gr : (long)(VSIZE - 1);
            ((float4*)&sX[r][0])[q] =
                ((const float4*)(table + rv * EDIM + 32 * h))[q];
        }
        __syncthreads();

#pragma unroll 4
        for (int k4 = 0; k4 < 8; k4++) {
            float4 xv0 = *(const float4*)&sX[4 * rg + 0][4 * k4];
            float4 xv1 = *(const float4*)&sX[4 * rg + 1][4 * k4];
            float4 xv2 = *(const float4*)&sX[4 * rg + 2][4 * k4];
            float4 xv3 = *(const float4*)&sX[4 * rg + 3][4 * k4];
            const float* xp0 = (const float*)&xv0;
            const float* xp1 = (const float*)&xv1;
            const float* xp2 = (const float*)&xv2;
            const float* xp3 = (const float*)&xv3;
#pragma unroll
            for (int kk = 0; kk < 4; kk++) {
                ulonglong2 wA = *(const ulonglong2*)&sWt[4 * k4 + kk][4 * dg];
                ulonglong2 wB = *(const ulonglong2*)&sWt[4 * k4 + kk][32 + 4 * dg];
                ull x0 = dup2(xp0[kk]);
                aA[0][0] = ffma2(wA.x, x0, aA[0][0]); aA[0][1] = ffma2(wA.y, x0, aA[0][1]);
                aB[0][0] = ffma2(wB.x, x0, aB[0][0]); aB[0][1] = ffma2(wB.y, x0, aB[0][1]);
                ull x1 = dup2(xp1[kk]);
                aA[1][0] = ffma2(wA.x, x1, aA[1][0]); aA[1][1] = ffma2(wA.y, x1, aA[1][1]);
                aB[1][0] = ffma2(wB.x, x1, aB[1][0]); aB[1][1] = ffma2(wB.y, x1, aB[1][1]);
                ull x2 = dup2(xp2[kk]);
                aA[2][0] = ffma2(wA.x, x2, aA[2][0]); aA[2][1] = ffma2(wA.y, x2, aA[2][1]);
                aB[2][0] = ffma2(wB.x, x2, aB[2][0]); aB[2][1] = ffma2(wB.y, x2, aB[2][1]);
                ull x3 = dup2(xp3[kk]);
                aA[3][0] = ffma2(wA.x, x3, aA[3][0]); aA[3][1] = ffma2(wA.y, x3, aA[3][1]);
                aB[3][0] = ffma2(wB.x, x3, aB[3][0]); aB[3][1] = ffma2(wB.y, x3, aB[3][1]);
            }
        }
    }
    __syncthreads();   // sX dead -> arena becomes sOut

    {
        float4 bA = *(const float4*)(bias + 4 * dg);
        float4 bB;
        if (32 + 4 * dg < DA) bB = *(const float4*)(bias + 32 + 4 * dg);
        else                  bB = make_float4(0.f, 0.f, 0.f, 0.f);
#pragma unroll
        for (int j = 0; j < 4; j++) {
            int r = 4 * rg + j;
            float2 p = upk(aA[j][0]), q = upk(aA[j][1]);
            *(float4*)&sOut[r][4 * dg] =
                make_float4(p.x + bA.x, p.y + bA.y, q.x + bA.z, q.y + bA.w);
            p = upk(aB[j][0]); q = upk(aB[j][1]);
            *(float4*)&sOut[r][32 + 4 * dg] =
                make_float4(p.x + bB.x, p.y + bB.y, q.x + bB.z, q.y + bB.w);
        }
    }
    __syncthreads();

    // normalize + store PADDED rows: warp w handles rows 16w..16w+15
    int w = tid >> 5, l = tid & 31;
    float* outp = GATHER ? g_tprojn : g_cprojn;
#pragma unroll
    for (int rr = 0; rr < 16; rr++) {
        int r = 16 * w + rr;
        long gr = base + r;
        float v0 = sOut[r][l];
        float v1 = (l < DA - 32) ? sOut[r][l + 32] : 0.f;
        float ss = v0 * v0 + v1 * v1;
#pragma unroll
        for (int o = 16; o >= 1; o >>= 1)
            ss += __shfl_xor_sync(0xffffffffu, ss, o);
        float inv = 1.0f / fmaxf(sqrtf(ss), EPSV);
        if (!GATHER && gr >= VSIZE) continue;
        float* op = outp + gr * DAP;
        op[l] = v0 * inv;
        op[l + 32] = v1 * inv;       // zero for l>=28 -> pads cols 60..63
    }
}

// ---------------------------------------------------------------------------
// Kernel 3: main. One CTA per batch row (R10 version, unchanged).
// ---------------------------------------------------------------------------
__global__ __launch_bounds__(256, 4)
void main_kernel(const float* __restrict__ cvec,
                 const int* __restrict__ citems,
                 const int* __restrict__ maskp,
                 float* __restrict__ outS)
{
    __shared__ int   s_cit[CN];
    __shared__ int   s_mask[CN];
    __shared__ __align__(16) float s_tp[TN][DAP];
    __shared__ __align__(16) float s_aT[CN][8];            // attn [c][t]
    __shared__ __align__(16) char  arena[8 * 4 * 128 * 8]; // s_cp (27.2K) / s_part (32K ull)
    float (*s_cp)[68] = (float(*)[68])arena;
    ull* sp = (ull*)arena;                                 // [w][tp][e] packed t-pairs

    int b = blockIdx.x;
    int tid = threadIdx.x;
    int w = tid >> 5, l = tid & 31;

    if (tid < CN) {
        s_cit[tid]  = citems[b * CN + tid];
        s_mask[tid] = maskp[b * CN + tid];
    }
    for (int i = tid; i < TN * DAP; i += 256)
        ((float*)s_tp)[i] = g_tprojn[(size_t)b * (TN * DAP) + i];

    // ---- Phase 1: scores; warp w = t, lanes own c-columns ----
    float sc[8];
#pragma unroll
    for (int i = 0; i < 8; i++) sc[i] = -1e30f;

    for (int ch = 0; ch < 2; ch++) {
        __syncthreads();
        int base = ch * CCH;
        for (int r = w; r < CCH; r += 8) {
            int tok = s_cit[base + r];
            if (l < 30) {
                float2 v = ((const float2*)(g_cprojn + (size_t)tok * DAP))[l];
                *(float2*)&s_cp[r][2 * l] = v;
            }
        }
        __syncthreads();

        ull a0 = 0, a1 = 0, a2 = 0, a3 = 0;
#pragma unroll
        for (int d4 = 0; d4 < 15; d4++) {
            ulonglong2 tp = *(const ulonglong2*)&s_tp[w][4 * d4];
            ulonglong2 c0 = *(const ulonglong2*)&s_cp[l][4 * d4];
            a0 = ffma2(c0.x, tp.x, a0); a0 = ffma2(c0.y, tp.y, a0);
            ulonglong2 c1 = *(const ulonglong2*)&s_cp[l + 32][4 * d4];
            a1 = ffma2(c1.x, tp.x, a1); a1 = ffma2(c1.y, tp.y, a1);
            ulonglong2 c2 = *(const ulonglong2*)&s_cp[l + 64][4 * d4];
            a2 = ffma2(c2.x, tp.x, a2); a2 = ffma2(c2.y, tp.y, a2);
            if (l < 4) {
                ulonglong2 c3 = *(const ulonglong2*)&s_cp[l + 96][4 * d4];
                a3 = ffma2(c3.x, tp.x, a3); a3 = ffma2(c3.y, tp.y, a3);
            }
        }
        {
            float2 f;
            f = upk(a0); sc[ch*4+0] = s_mask[base + l]      ? -1e30f : (f.x + f.y);
            f = upk(a1); sc[ch*4+1] = s_mask[base + l + 32] ? -1e30f : (f.x + f.y);
            f = upk(a2); sc[ch*4+2] = s_mask[base + l + 64] ? -1e30f : (f.x + f.y);
            if (l < 4) {
                f = upk(a3); sc[ch*4+3] = s_mask[base + l + 96] ? -1e30f : (f.x + f.y);
            }
        }
    }

    // ---- Phase 2: softmax over c for t=w ----
    {
        float m = sc[0];
#pragma unroll
        for (int i = 1; i < 8; i++) m = fmaxf(m, sc[i]);
#pragma unroll
        for (int o = 16; o >= 1; o >>= 1)
            m = fmaxf(m, __shfl_xor_sync(0xffffffffu, m, o));
        float sum = 0.f;
#pragma unroll
        for (int i = 0; i < 8; i++) { sc[i] = __expf(sc[i] - m); sum += sc[i]; }
#pragma unroll
        for (int o = 16; o >= 1; o >>= 1)
            sum += __shfl_xor_sync(0xffffffffu, sum, o);
        float inv = 1.0f / sum;
#pragma unroll
        for (int i = 0; i < 8; i++) {
            int cl = l + 32 * (i & 3);
            if (cl < CCH) s_aT[(i >> 2) * CCH + cl][w] = sc[i] * inv;
        }
    }
    __syncthreads();   // fences s_cp reads before sp writes

    // ---- Phase 3: partial s over warp's 25-c chunk; lane owns e=4l..4l+3.
    //      Accumulators packed over t-pairs: acc[tp][e] (tp = (2t,2t+1)).
    {
        ull acc[4][4];
#pragma unroll
        for (int i = 0; i < 4; i++)
            acc[i][0] = acc[i][1] = acc[i][2] = acc[i][3] = 0;
        int cbeg = 25 * w;
#pragma unroll 5
        for (int c = cbeg; c < cbeg + 25; c++) {
            int tok = s_cit[c];
            float4 u = *(const float4*)(cvec + (size_t)tok * EDIM + 4 * l);
            ull ud0 = dup2(u.x), ud1 = dup2(u.y), ud2 = dup2(u.z), ud3 = dup2(u.w);
            ulonglong2 A = *(const ulonglong2*)&s_aT[c][0];  // (t0,t1),(t2,t3)
            ulonglong2 B = *(const ulonglong2*)&s_aT[c][4];  // (t4,t5),(t6,t7)
            acc[0][0] = ffma2(A.x, ud0, acc[0][0]);
            acc[0][1] = ffma2(A.x, ud1, acc[0][1]);
            acc[0][2] = ffma2(A.x, ud2, acc[0][2]);
            acc[0][3] = ffma2(A.x, ud3, acc[0][3]);
            acc[1][0] = ffma2(A.y, ud0, acc[1][0]);
            acc[1][1] = ffma2(A.y, ud1, acc[1][1]);
            acc[1][2] = ffma2(A.y, ud2, acc[1][2]);
            acc[1][3] = ffma2(A.y, ud3, acc[1][3]);
            acc[2][0] = ffma2(B.x, ud0, acc[2][0]);
            acc[2][1] = ffma2(B.x, ud1, acc[2][1]);
            acc[2][2] = ffma2(B.x, ud2, acc[2][2]);
            acc[2][3] = ffma2(B.x, ud3, acc[2][3]);
            acc[3][0] = ffma2(B.y, ud0, acc[3][0]);
            acc[3][1] = ffma2(B.y, ud1, acc[3][1]);
            acc[3][2] = ffma2(B.y, ud2, acc[3][2]);
            acc[3][3] = ffma2(B.y, ud3, acc[3][3]);
        }
#pragma unroll
        for (int tp = 0; tp < 4; tp++) {
            ulonglong2 v0; v0.x = acc[tp][0]; v0.y = acc[tp][1];
            ulonglong2 v1; v1.x = acc[tp][2]; v1.y = acc[tp][3];
            *(ulonglong2*)&sp[((size_t)(w * 4 + tp)) * 128 + 4 * l]     = v0;
            *(ulonglong2*)&sp[((size_t)(w * 4 + tp)) * 128 + 4 * l + 2] = v1;
        }
    }
    __syncthreads();

    // ---- reduce 8 warp-partials (packed), write S ----
#pragma unroll
    for (int q = 0; q < 2; q++) {
        int s = tid + 256 * q;            // 0..511 over (tp, e)
        int tp = s >> 7, e = s & 127;
        ull v = sp[(size_t)tp * 128 + e];
#pragma unroll
        for (int p = 1; p < 8; p++)
            v = add2(v, sp[((size_t)(p * 4 + tp)) * 128 + e]);
        float2 f = upk(v);
        float* op = outS + (size_t)b * (TN * EDIM) + (2 * tp) * EDIM + e;
        op[0]    = f.x;
        op[EDIM] = f.y;
    }
}

// ---------------------------------------------------------------------------
// Kernel 4: Z = S @ Mt + bias2  ([32768,128] x [128,128]), 64 rows per CTA.
// ---------------------------------------------------------------------------
__global__ __launch_bounds__(256)
void zgemm_kernel(const float* __restrict__ S, float* __restrict__ outp)
{
    __shared__ __align__(16) float sS[64][128];

    int tid = threadIdx.x;
    int rg = tid >> 4;
    int eg = tid & 15;
    long row0 = (long)blockIdx.x * 64;

    for (int i = tid; i < 64 * 32; i += 256) {
        int r = i >> 5, q = i & 31;
        ((float4*)&sS[r][0])[q] = ((const float4*)(S + (row0 + r) * EDIM))[q];
    }

    ull acc[4][4];
    {
        const ulonglong2* bp = (const ulonglong2*)(g_bias2 + 8 * eg);
        ulonglong2 b0 = bp[0], b1 = bp[1];
#pragma unroll
        for (int j = 0; j < 4; j++) {
            acc[j][0] = b0.x; acc[j][1] = b0.y;
            acc[j][2] = b1.x; acc[j][3] = b1.y;
        }
    }
    __syncthreads();

#pragma unroll 4
    for (int k = 0; k < EDIM; k++) {
        const ulonglong2* mp = (const ulonglong2*)(g_Mt + k * EDIM + 8 * eg);
        ulonglong2 m0 = mp[0], m1 = mp[1];
        ull x0 = dup2(sS[4 * rg + 0][k]);
        ull x1 = dup2(sS[4 * rg + 1][k]);
        ull x2 = dup2(sS[4 * rg + 2][k]);
        ull x3 = dup2(sS[4 * rg + 3][k]);
        acc[0][0] = ffma2(m0.x, x0, acc[0][0]); acc[0][1] = ffma2(m0.y, x0, acc[0][1]);
        acc[0][2] = ffma2(m1.x, x0, acc[0][2]); acc[0][3] = ffma2(m1.y, x0, acc[0][3]);
        acc[1][0] = ffma2(m0.x, x1, acc[1][0]); acc[1][1] = ffma2(m0.y, x1, acc[1][1]);
        acc[1][2] = ffma2(m1.x, x1, acc[1][2]); acc[1][3] = ffma2(m1.y, x1, acc[1][3]);
        acc[2][0] = ffma2(m0.x, x2, acc[2][0]); acc[2][1] = ffma2(m0.y, x2, acc[2][1]);
        acc[2][2] = ffma2(m1.x, x2, acc[2][2]); acc[2][3] = ffma2(m1.y, x2, acc[2][3]);
        acc[3][0] = ffma2(m0.x, x3, acc[3][0]); acc[3][1] = ffma2(m0.y, x3, acc[3][1]);
        acc[3][2] = ffma2(m1.x, x3, acc[3][2]); acc[3][3] = ffma2(m1.y, x3, acc[3][3]);
    }

#pragma unroll
    for (int j = 0; j < 4; j++) {
        float* op = outp + (row0 + 4 * rg + j) * EDIM + 8 * eg;
        float2 f0 = upk(acc[j][0]), f1 = upk(acc[j][1]);
        float2 f2 = upk(acc[j][2]), f3 = upk(acc[j][3]);
        *(float4*)(op)     = make_float4(f0.x, f0.y, f1.x, f1.y);
        *(float4*)(op + 4) = make_float4(f2.x, f2.y, f3.x, f3.y);
    }
}

// ---------------------------------------------------------------------------
extern "C" void kernel_launch(void* const* d_in, const int* in_sizes, int n_in,
                              void* d_out, int out_size)
{
    const float* tvec  = (const float*)d_in[0];
    const float* cvec  = (const float*)d_in[1];
    const float* Ac_w  = (const float*)d_in[2];
    const float* Ac_b  = (const float*)d_in[3];
    const float* At_w  = (const float*)d_in[4];
    const float* At_b  = (const float*)d_in[5];
    const float* Bc_w  = (const float*)d_in[6];
    const float* Bc_b  = (const float*)d_in[7];
    const float* R_w   = (const float*)d_in[8];
    const float* R_b   = (const float*)d_in[9];
    const int*   titems = (const int*)d_in[10];
    const int*   citems = (const int*)d_in[11];
    const int*   maskp  = (const int*)d_in[12];

    float* S;
    cudaGetSymbolAddress((void**)&S, g_S);

    fuse_kernel<<<EDIM, EDIM>>>(R_w, Bc_w, Bc_b, R_b);
    proj_kernel<false><<<(VSIZE + 127) / 128, 256>>>(cvec, Ac_w, Ac_b, nullptr);
    proj_kernel<true><<<(BN * TN) / 128, 256>>>(tvec, At_w, At_b, titems);
    main_kernel<<<BN, 256>>>(cvec, citems, maskp, S);
    zgemm_kernel<<<(BN * TN) / 64, 256>>>(S, (float*)d_out);
}

// round 13
// speedup vs baseline: 1.0221x; 1.0221x over previous
#include <cuda_runtime.h>
#include <cstdint>

#define VSIZE 100000
#define EDIM  128
#define DA    60
#define DAP   64            // padded projection row (256B aligned)
#define BN    4096
#define TN    8
#define CN    200
#define EPSV  1e-6f
#define CCH   100

typedef unsigned long long ull;

// Scratch (device globals: no allocation allowed)
__device__ float g_cprojn[(size_t)VSIZE * DAP];    // normalized c projections [V,64p]
__device__ float g_tprojn[(size_t)BN * TN * DAP];  // normalized t projections [B*T,64p]
__device__ float g_Mt[EDIM * EDIM];                // Mt[k][e] = (R_w @ Bc_w)[e][k]
__device__ float g_bias2[EDIM];                    // R_w @ Bc_b + R_b
__device__ float g_S[(size_t)BN * TN * EDIM];      // attn @ u   [B*T,128]

// ---------------------------------------------------------------------------
// packed fp32x2 helpers
// ---------------------------------------------------------------------------
__device__ __forceinline__ ull ffma2(ull a, ull b, ull c) {
    ull d; asm("fma.rn.f32x2 %0,%1,%2,%3;" : "=l"(d) : "l"(a), "l"(b), "l"(c));
    return d;
}
__device__ __forceinline__ ull add2(ull a, ull b) {
    ull d; asm("add.rn.f32x2 %0,%1,%2;" : "=l"(d) : "l"(a), "l"(b));
    return d;
}
__device__ __forceinline__ ull dup2(float x) {
    ull r; asm("mov.b64 %0,{%1,%1};" : "=l"(r) : "f"(x)); return r;
}
__device__ __forceinline__ float2 upk(ull v) {
    float a, b; asm("mov.b64 {%0,%1},%2;" : "=f"(a), "=f"(b) : "l"(v));
    return make_float2(a, b);
}

// ---------------------------------------------------------------------------
// Kernel 0: fuse M = R_w @ Bc_w (stored transposed) and bias2 = R_w@Bc_b + R_b
// ---------------------------------------------------------------------------
__global__ void fuse_kernel(const float* __restrict__ Rw, const float* __restrict__ Bw,
                            const float* __restrict__ Bb, const float* __restrict__ Rb)
{
    int e = blockIdx.x;
    int k = threadIdx.x;
    __shared__ float sR[EDIM];
    __shared__ float sP[EDIM];
    sR[k] = Rw[e * EDIM + k];
    __syncthreads();
    float acc = 0.f;
#pragma unroll 8
    for (int j = 0; j < EDIM; j++)
        acc = fmaf(sR[j], Bw[j * EDIM + k], acc);
    g_Mt[k * EDIM + e] = acc;
    sP[k] = sR[k] * Bb[k];
    __syncthreads();
    if (k == 0) {
        float s = 0.f;
        for (int j = 0; j < EDIM; j++) s += sP[j];
        g_bias2[e] = s + Rb[e];
    }
}

// ---------------------------------------------------------------------------
// Kernel 1/2: project 128 rows/CTA through W[60,128]+bias, eps-clamped L2 norm.
// Micro-tile 4r x 8d. k in 4 quarters of 32. PADDED smem rows (68) so warp
// row-groups land 16 banks apart (2-way worst case, not 4-way).
// Static smem = 8.7K (sWt) + 34.8K (arena) = 43.5KB.
// Writes PADDED global rows (DAP=64 floats; cols 60..63 = 0).
// ---------------------------------------------------------------------------
template <bool GATHER>
__global__ __launch_bounds__(256)
void proj_kernel(const float* __restrict__ table,
                 const float* __restrict__ W,
                 const float* __restrict__ bias,
                 const int* __restrict__ idx)
{
    __shared__ __align__(16) float sWt[32][68];         // 8.7 KB (k-quarter x d)
    __shared__ __align__(16) char  arena[128 * 68 * 4]; // 34.8 KB: sX then sOut
    float (*sX)[68]   = (float(*)[68])arena;
    float (*sOut)[68] = (float(*)[68])arena;

    int tid = threadIdx.x;
    int rg = tid >> 3, dg = tid & 7;          // rows 4rg..4rg+3, d-cols 4dg / 32+4dg
    long base = (long)blockIdx.x * 128;

    ull aA[4][2], aB[4][2];
#pragma unroll
    for (int j = 0; j < 4; j++) { aA[j][0] = aA[j][1] = aB[j][0] = aB[j][1] = 0; }

#pragma unroll
    for (int h = 0; h < 4; h++) {
        __syncthreads();
        // stage W quarter transposed, d-consecutive (W is L2-hot)
        for (int i = tid; i < 32 * 64; i += 256) {
            int kk = i >> 6, d = i & 63;
            sWt[kk][d] = (d < DA) ? W[d * EDIM + 32 * h + kk] : 0.f;
        }
        // stage x quarter: 128 rows x 32 floats (8 float4 per row)
        for (int i = tid; i < 128 * 8; i += 256) {
            int r = i >> 3, q = i & 7;
            long gr = base + r;
            long rv;
            if (GATHER) rv = (long)idx[gr];
            else        rv = (gr < VSIZE) ? gr : (long)(VSIZE - 1);
            *(float4*)&sX[r][4 * q] =
                ((const float4*)(table + rv * EDIM + 32 * h))[q];
        }
        __syncthreads();

#pragma unroll 4
        for (int k4 = 0; k4 < 8; k4++) {
            float4 xv0 = *(const float4*)&sX[4 * rg + 0][4 * k4];
            float4 xv1 = *(const float4*)&sX[4 * rg + 1][4 * k4];
            float4 xv2 = *(const float4*)&sX[4 * rg + 2][4 * k4];
            float4 xv3 = *(const float4*)&sX[4 * rg + 3][4 * k4];
            const float* xp0 = (const float*)&xv0;
            const float* xp1 = (const float*)&xv1;
            const float* xp2 = (const float*)&xv2;
            const float* xp3 = (const float*)&xv3;
#pragma unroll
            for (int kk = 0; kk < 4; kk++) {
                ulonglong2 wA = *(const ulonglong2*)&sWt[4 * k4 + kk][4 * dg];
                ulonglong2 wB = *(const ulonglong2*)&sWt[4 * k4 + kk][32 + 4 * dg];
                ull x0 = dup2(xp0[kk]);
                aA[0][0] = ffma2(wA.x, x0, aA[0][0]); aA[0][1] = ffma2(wA.y, x0, aA[0][1]);
                aB[0][0] = ffma2(wB.x, x0, aB[0][0]); aB[0][1] = ffma2(wB.y, x0, aB[0][1]);
                ull x1 = dup2(xp1[kk]);
                aA[1][0] = ffma2(wA.x, x1, aA[1][0]); aA[1][1] = ffma2(wA.y, x1, aA[1][1]);
                aB[1][0] = ffma2(wB.x, x1, aB[1][0]); aB[1][1] = ffma2(wB.y, x1, aB[1][1]);
                ull x2 = dup2(xp2[kk]);
                aA[2][0] = ffma2(wA.x, x2, aA[2][0]); aA[2][1] = ffma2(wA.y, x2, aA[2][1]);
                aB[2][0] = ffma2(wB.x, x2, aB[2][0]); aB[2][1] = ffma2(wB.y, x2, aB[2][1]);
                ull x3 = dup2(xp3[kk]);
                aA[3][0] = ffma2(wA.x, x3, aA[3][0]); aA[3][1] = ffma2(wA.y, x3, aA[3][1]);
                aB[3][0] = ffma2(wB.x, x3, aB[3][0]); aB[3][1] = ffma2(wB.y, x3, aB[3][1]);
            }
        }
    }
    __syncthreads();   // sX dead -> arena becomes sOut

    {
        float4 bA = *(const float4*)(bias + 4 * dg);
        float4 bB;
        if (32 + 4 * dg < DA) bB = *(const float4*)(bias + 32 + 4 * dg);
        else                  bB = make_float4(0.f, 0.f, 0.f, 0.f);
#pragma unroll
        for (int j = 0; j < 4; j++) {
            int r = 4 * rg + j;
            float2 p = upk(aA[j][0]), q = upk(aA[j][1]);
            *(float4*)&sOut[r][4 * dg] =
                make_float4(p.x + bA.x, p.y + bA.y, q.x + bA.z, q.y + bA.w);
            p = upk(aB[j][0]); q = upk(aB[j][1]);
            *(float4*)&sOut[r][32 + 4 * dg] =
                make_float4(p.x + bB.x, p.y + bB.y, q.x + bB.z, q.y + bB.w);
        }
    }
    __syncthreads();

    // normalize + store PADDED rows: warp w handles rows 16w..16w+15
    int w = tid >> 5, l = tid & 31;
    float* outp = GATHER ? g_tprojn : g_cprojn;
#pragma unroll
    for (int rr = 0; rr < 16; rr++) {
        int r = 16 * w + rr;
        long gr = base + r;
        float v0 = sOut[r][l];
        float v1 = (l < DA - 32) ? sOut[r][l + 32] : 0.f;
        float ss = v0 * v0 + v1 * v1;
#pragma unroll
        for (int o = 16; o >= 1; o >>= 1)
            ss += __shfl_xor_sync(0xffffffffu, ss, o);
        float inv = 1.0f / fmaxf(sqrtf(ss), EPSV);
        if (!GATHER && gr >= VSIZE) continue;
        float* op = outp + gr * DAP;
        op[l] = v0 * inv;
        op[l + 32] = v1 * inv;       // zero for l>=28 -> pads cols 60..63
    }
}

// ---------------------------------------------------------------------------
// Kernel 3: main. One CTA per batch row (R10 version, unchanged).
// ---------------------------------------------------------------------------
__global__ __launch_bounds__(256, 4)
void main_kernel(const float* __restrict__ cvec,
                 const int* __restrict__ citems,
                 const int* __restrict__ maskp,
                 float* __restrict__ outS)
{
    __shared__ int   s_cit[CN];
    __shared__ int   s_mask[CN];
    __shared__ __align__(16) float s_tp[TN][DAP];
    __shared__ __align__(16) float s_aT[CN][8];            // attn [c][t]
    __shared__ __align__(16) char  arena[8 * 4 * 128 * 8]; // s_cp (27.2K) / s_part (32K ull)
    float (*s_cp)[68] = (float(*)[68])arena;
    ull* sp = (ull*)arena;                                 // [w][tp][e] packed t-pairs

    int b = blockIdx.x;
    int tid = threadIdx.x;
    int w = tid >> 5, l = tid & 31;

    if (tid < CN) {
        s_cit[tid]  = citems[b * CN + tid];
        s_mask[tid] = maskp[b * CN + tid];
    }
    for (int i = tid; i < TN * DAP; i += 256)
        ((float*)s_tp)[i] = g_tprojn[(size_t)b * (TN * DAP) + i];

    // ---- Phase 1: scores; warp w = t, lanes own c-columns ----
    float sc[8];
#pragma unroll
    for (int i = 0; i < 8; i++) sc[i] = -1e30f;

    for (int ch = 0; ch < 2; ch++) {
        __syncthreads();
        int base = ch * CCH;
        for (int r = w; r < CCH; r += 8) {
            int tok = s_cit[base + r];
            if (l < 30) {
                float2 v = ((const float2*)(g_cprojn + (size_t)tok * DAP))[l];
                *(float2*)&s_cp[r][2 * l] = v;
            }
        }
        __syncthreads();

        ull a0 = 0, a1 = 0, a2 = 0, a3 = 0;
#pragma unroll
        for (int d4 = 0; d4 < 15; d4++) {
            ulonglong2 tp = *(const ulonglong2*)&s_tp[w][4 * d4];
            ulonglong2 c0 = *(const ulonglong2*)&s_cp[l][4 * d4];
            a0 = ffma2(c0.x, tp.x, a0); a0 = ffma2(c0.y, tp.y, a0);
            ulonglong2 c1 = *(const ulonglong2*)&s_cp[l + 32][4 * d4];
            a1 = ffma2(c1.x, tp.x, a1); a1 = ffma2(c1.y, tp.y, a1);
            ulonglong2 c2 = *(const ulonglong2*)&s_cp[l + 64][4 * d4];
            a2 = ffma2(c2.x, tp.x, a2); a2 = ffma2(c2.y, tp.y, a2);
            if (l < 4) {
                ulonglong2 c3 = *(const ulonglong2*)&s_cp[l + 96][4 * d4];
                a3 = ffma2(c3.x, tp.x, a3); a3 = ffma2(c3.y, tp.y, a3);
            }
        }
        {
            float2 f;
            f = upk(a0); sc[ch*4+0] = s_mask[base + l]      ? -1e30f : (f.x + f.y);
            f = upk(a1); sc[ch*4+1] = s_mask[base + l + 32] ? -1e30f : (f.x + f.y);
            f = upk(a2); sc[ch*4+2] = s_mask[base + l + 64] ? -1e30f : (f.x + f.y);
            if (l < 4) {
                f = upk(a3); sc[ch*4+3] = s_mask[base + l + 96] ? -1e30f : (f.x + f.y);
            }
        }
    }

    // ---- Phase 2: softmax over c for t=w ----
    {
        float m = sc[0];
#pragma unroll
        for (int i = 1; i < 8; i++) m = fmaxf(m, sc[i]);
#pragma unroll
        for (int o = 16; o >= 1; o >>= 1)
            m = fmaxf(m, __shfl_xor_sync(0xffffffffu, m, o));
        float sum = 0.f;
#pragma unroll
        for (int i = 0; i < 8; i++) { sc[i] = __expf(sc[i] - m); sum += sc[i]; }
#pragma unroll
        for (int o = 16; o >= 1; o >>= 1)
            sum += __shfl_xor_sync(0xffffffffu, sum, o);
        float inv = 1.0f / sum;
#pragma unroll
        for (int i = 0; i < 8; i++) {
            int cl = l + 32 * (i & 3);
            if (cl < CCH) s_aT[(i >> 2) * CCH + cl][w] = sc[i] * inv;
        }
    }
    __syncthreads();   // fences s_cp reads before sp writes

    // ---- Phase 3: partial s over warp's 25-c chunk; lane owns e=4l..4l+3.
    //      Accumulators packed over t-pairs: acc[tp][e] (tp = (2t,2t+1)).
    {
        ull acc[4][4];
#pragma unroll
        for (int i = 0; i < 4; i++)
            acc[i][0] = acc[i][1] = acc[i][2] = acc[i][3] = 0;
        int cbeg = 25 * w;
#pragma unroll 5
        for (int c = cbeg; c < cbeg + 25; c++) {
            int tok = s_cit[c];
            float4 u = *(const float4*)(cvec + (size_t)tok * EDIM + 4 * l);
            ull ud0 = dup2(u.x), ud1 = dup2(u.y), ud2 = dup2(u.z), ud3 = dup2(u.w);
            ulonglong2 A = *(const ulonglong2*)&s_aT[c][0];  // (t0,t1),(t2,t3)
            ulonglong2 B = *(const ulonglong2*)&s_aT[c][4];  // (t4,t5),(t6,t7)
            acc[0][0] = ffma2(A.x, ud0, acc[0][0]);
            acc[0][1] = ffma2(A.x, ud1, acc[0][1]);
            acc[0][2] = ffma2(A.x, ud2, acc[0][2]);
            acc[0][3] = ffma2(A.x, ud3, acc[0][3]);
            acc[1][0] = ffma2(A.y, ud0, acc[1][0]);
            acc[1][1] = ffma2(A.y, ud1, acc[1][1]);
            acc[1][2] = ffma2(A.y, ud2, acc[1][2]);
            acc[1][3] = ffma2(A.y, ud3, acc[1][3]);
            acc[2][0] = ffma2(B.x, ud0, acc[2][0]);
            acc[2][1] = ffma2(B.x, ud1, acc[2][1]);
            acc[2][2] = ffma2(B.x, ud2, acc[2][2]);
            acc[2][3] = ffma2(B.x, ud3, acc[2][3]);
            acc[3][0] = ffma2(B.y, ud0, acc[3][0]);
            acc[3][1] = ffma2(B.y, ud1, acc[3][1]);
            acc[3][2] = ffma2(B.y, ud2, acc[3][2]);
            acc[3][3] = ffma2(B.y, ud3, acc[3][3]);
        }
#pragma unroll
        for (int tp = 0; tp < 4; tp++) {
            ulonglong2 v0; v0.x = acc[tp][0]; v0.y = acc[tp][1];
            ulonglong2 v1; v1.x = acc[tp][2]; v1.y = acc[tp][3];
            *(ulonglong2*)&sp[((size_t)(w * 4 + tp)) * 128 + 4 * l]     = v0;
            *(ulonglong2*)&sp[((size_t)(w * 4 + tp)) * 128 + 4 * l + 2] = v1;
        }
    }
    __syncthreads();

    // ---- reduce 8 warp-partials (packed), write S ----
#pragma unroll
    for (int q = 0; q < 2; q++) {
        int s = tid + 256 * q;            // 0..511 over (tp, e)
        int tp = s >> 7, e = s & 127;
        ull v = sp[(size_t)tp * 128 + e];
#pragma unroll
        for (int p = 1; p < 8; p++)
            v = add2(v, sp[((size_t)(p * 4 + tp)) * 128 + e]);
        float2 f = upk(v);
        float* op = outS + (size_t)b * (TN * EDIM) + (2 * tp) * EDIM + e;
        op[0]    = f.x;
        op[EDIM] = f.y;
    }
}

// ---------------------------------------------------------------------------
// Kernel 4: Z = S @ Mt + bias2  ([32768,128] x [128,128]), 64 rows per CTA.
// ---------------------------------------------------------------------------
__global__ __launch_bounds__(256)
void zgemm_kernel(const float* __restrict__ S, float* __restrict__ outp)
{
    __shared__ __align__(16) float sS[64][128];

    int tid = threadIdx.x;
    int rg = tid >> 4;
    int eg = tid & 15;
    long row0 = (long)blockIdx.x * 64;

    for (int i = tid; i < 64 * 32; i += 256) {
        int r = i >> 5, q = i & 31;
        ((float4*)&sS[r][0])[q] = ((const float4*)(S + (row0 + r) * EDIM))[q];
    }

    ull acc[4][4];
    {
        const ulonglong2* bp = (const ulonglong2*)(g_bias2 + 8 * eg);
        ulonglong2 b0 = bp[0], b1 = bp[1];
#pragma unroll
        for (int j = 0; j < 4; j++) {
            acc[j][0] = b0.x; acc[j][1] = b0.y;
            acc[j][2] = b1.x; acc[j][3] = b1.y;
        }
    }
    __syncthreads();

#pragma unroll 4
    for (int k = 0; k < EDIM; k++) {
        const ulonglong2* mp = (const ulonglong2*)(g_Mt + k * EDIM + 8 * eg);
        ulonglong2 m0 = mp[0], m1 = mp[1];
        ull x0 = dup2(sS[4 * rg + 0][k]);
        ull x1 = dup2(sS[4 * rg + 1][k]);
        ull x2 = dup2(sS[4 * rg + 2][k]);
        ull x3 = dup2(sS[4 * rg + 3][k]);
        acc[0][0] = ffma2(m0.x, x0, acc[0][0]); acc[0][1] = ffma2(m0.y, x0, acc[0][1]);
        acc[0][2] = ffma2(m1.x, x0, acc[0][2]); acc[0][3] = ffma2(m1.y, x0, acc[0][3]);
        acc[1][0] = ffma2(m0.x, x1, acc[1][0]); acc[1][1] = ffma2(m0.y, x1, acc[1][1]);
        acc[1][2] = ffma2(m1.x, x1, acc[1][2]); acc[1][3] = ffma2(m1.y, x1, acc[1][3]);
        acc[2][0] = ffma2(m0.x, x2, acc[2][0]); acc[2][1] = ffma2(m0.y, x2, acc[2][1]);
        acc[2][2] = ffma2(m1.x, x2, acc[2][2]); acc[2][3] = ffma2(m1.y, x2, acc[2][3]);
        acc[3][0] = ffma2(m0.x, x3, acc[3][0]); acc[3][1] = ffma2(m0.y, x3, acc[3][1]);
        acc[3][2] = ffma2(m1.x, x3, acc[3][2]); acc[3][3] = ffma2(m1.y, x3, acc[3][3]);
    }

#pragma unroll
    for (int j = 0; j < 4; j++) {
        float* op = outp + (row0 + 4 * rg + j) * EDIM + 8 * eg;
        float2 f0 = upk(acc[j][0]), f1 = upk(acc[j][1]);
        float2 f2 = upk(acc[j][2]), f3 = upk(acc[j][3]);
        *(float4*)(op)     = make_float4(f0.x, f0.y, f1.x, f1.y);
        *(float4*)(op + 4) = make_float4(f2.x, f2.y, f3.x, f3.y);
    }
}

// ---------------------------------------------------------------------------
extern "C" void kernel_launch(void* const* d_in, const int* in_sizes, int n_in,
                              void* d_out, int out_size)
{
    const float* tvec  = (const float*)d_in[0];
    const float* cvec  = (const float*)d_in[1];
    const float* Ac_w  = (const float*)d_in[2];
    const float* Ac_b  = (const float*)d_in[3];
    const float* At_w  = (const float*)d_in[4];
    const float* At_b  = (const float*)d_in[5];
    const float* Bc_w  = (const float*)d_in[6];
    const float* Bc_b  = (const float*)d_in[7];
    const float* R_w   = (const float*)d_in[8];
    const float* R_b   = (const float*)d_in[9];
    const int*   titems = (const int*)d_in[10];
    const int*   citems = (const int*)d_in[11];
    const int*   maskp  = (const int*)d_in[12];

    float* S;
    cudaGetSymbolAddress((void**)&S, g_S);

    fuse_kernel<<<EDIM, EDIM>>>(R_w, Bc_w, Bc_b, R_b);
    proj_kernel<false><<<(VSIZE + 127) / 128, 256>>>(cvec, Ac_w, Ac_b, nullptr);
    proj_kernel<true><<<(BN * TN) / 128, 256>>>(tvec, At_w, At_b, titems);
    main_kernel<<<BN, 256>>>(cvec, citems, maskp, S);
    zgemm_kernel<<<(BN * TN) / 64, 256>>>(S, (float*)d_out);
}

// round 14
// speedup vs baseline: 1.0263x; 1.0041x over previous
#include <cuda_runtime.h>
#include <cstdint>

#define VSIZE 100000
#define EDIM  128
#define DA    60
#define DAP   64            // padded projection row (256B aligned)
#define BN    4096
#define TN    8
#define CN    200
#define EPSV  1e-6f
#define CCH   100

typedef unsigned long long ull;

// Scratch (device globals: no allocation allowed)
__device__ float g_cprojn[(size_t)VSIZE * DAP];    // normalized c projections [V,64p]
__device__ float g_tprojn[(size_t)BN * TN * DAP];  // normalized t projections [B*T,64p]
__device__ float g_Mt[EDIM * EDIM];                // Mt[k][e] = (R_w @ Bc_w)[e][k]
__device__ float g_bias2[EDIM];                    // R_w @ Bc_b + R_b
__device__ float g_S[(size_t)BN * TN * EDIM];      // attn @ u   [B*T,128]

// ---------------------------------------------------------------------------
// packed fp32x2 helpers
// ---------------------------------------------------------------------------
__device__ __forceinline__ ull ffma2(ull a, ull b, ull c) {
    ull d; asm("fma.rn.f32x2 %0,%1,%2,%3;" : "=l"(d) : "l"(a), "l"(b), "l"(c));
    return d;
}
__device__ __forceinline__ ull add2(ull a, ull b) {
    ull d; asm("add.rn.f32x2 %0,%1,%2;" : "=l"(d) : "l"(a), "l"(b));
    return d;
}
__device__ __forceinline__ ull dup2(float x) {
    ull r; asm("mov.b64 %0,{%1,%1};" : "=l"(r) : "f"(x)); return r;
}
__device__ __forceinline__ float2 upk(ull v) {
    float a, b; asm("mov.b64 {%0,%1},%2;" : "=f"(a), "=f"(b) : "l"(v));
    return make_float2(a, b);
}

// ---------------------------------------------------------------------------
// Kernel 0: fuse M = R_w @ Bc_w (stored transposed) and bias2 = R_w@Bc_b + R_b
// ---------------------------------------------------------------------------
__global__ void fuse_kernel(const float* __restrict__ Rw, const float* __restrict__ Bw,
                            const float* __restrict__ Bb, const float* __restrict__ Rb)
{
    int e = blockIdx.x;
    int k = threadIdx.x;
    __shared__ float sR[EDIM];
    __shared__ float sP[EDIM];
    sR[k] = Rw[e * EDIM + k];
    __syncthreads();
    float acc = 0.f;
#pragma unroll 8
    for (int j = 0; j < EDIM; j++)
        acc = fmaf(sR[j], Bw[j * EDIM + k], acc);
    g_Mt[k * EDIM + e] = acc;
    sP[k] = sR[k] * Bb[k];
    __syncthreads();
    if (k == 0) {
        float s = 0.f;
        for (int j = 0; j < EDIM; j++) s += sP[j];
        g_bias2[e] = s + Rb[e];
    }
}

// ---------------------------------------------------------------------------
// Kernel 1/2: project 64 rows/CTA through W[60,128]+bias, eps-clamped L2 norm.
// (R10 version — proven fastest proj so far.)
// Writes PADDED rows (DAP=64 floats; cols 60..63 = 0).
// ---------------------------------------------------------------------------
template <bool GATHER>
__global__ __launch_bounds__(256)
void proj_kernel(const float* __restrict__ table,
                 const float* __restrict__ W,
                 const float* __restrict__ bias,
                 const int* __restrict__ idx)
{
    __shared__ __align__(16) float sWt[64][68];
    __shared__ __align__(16) char  arena[64 * 68 * 4];
    float (*sX)[68]   = (float(*)[68])arena;
    float (*sOut)[68] = (float(*)[68])arena;

    int tid = threadIdx.x;
    int rg = tid >> 3, dg = tid & 7;
    int r0 = 2 * rg, r1 = r0 + 1;
    long base = (long)blockIdx.x * 64;

    ull aA0 = 0, aA1 = 0, aB0 = 0, aB1 = 0;
    ull bA0 = 0, bA1 = 0, bB0 = 0, bB1 = 0;

#pragma unroll
    for (int h = 0; h < 2; h++) {
        __syncthreads();
        for (int i = tid; i < DA * 64; i += 256) {
            int d = i >> 6, kk = i & 63;
            sWt[kk][d] = W[d * EDIM + 64 * h + kk];
        }
        for (int i = tid; i < 64 * 4; i += 256)
            sWt[i >> 2][60 + (i & 3)] = 0.f;
        for (int i = tid; i < 64 * 16; i += 256) {
            int r = i >> 4, q = i & 15;
            long gr = base + r;
            long rv = GATHER ? (long)idx[gr] : (gr < VSIZE ? gr : (long)(VSIZE - 1));
            ((float4*)&sX[r][0])[q] =
                ((const float4*)(table + rv * EDIM + 64 * h))[q];
        }
        __syncthreads();

#pragma unroll 8
        for (int k = 0; k < 64; k++) {
            ulonglong2 wA = *(const ulonglong2*)&sWt[k][4 * dg];
            ulonglong2 wB = *(const ulonglong2*)&sWt[k][32 + 4 * dg];
            ull x0 = dup2(sX[r0][k]);
            ull x1 = dup2(sX[r1][k]);
            aA0 = ffma2(wA.x, x0, aA0); aA1 = ffma2(wA.y, x0, aA1);
            aB0 = ffma2(wB.x, x0, aB0); aB1 = ffma2(wB.y, x0, aB1);
            bA0 = ffma2(wA.x, x1, bA0); bA1 = ffma2(wA.y, x1, bA1);
            bB0 = ffma2(wB.x, x1, bB0); bB1 = ffma2(wB.y, x1, bB1);
        }
    }
    __syncthreads();

    {
        float4 bA = *(const float4*)(bias + 4 * dg);
        float4 bB;
        if (32 + 4 * dg < DA) bB = *(const float4*)(bias + 32 + 4 * dg);
        else                  bB = make_float4(0.f, 0.f, 0.f, 0.f);
        float2 p, q;
        p = upk(aA0); q = upk(aA1);
        *(float4*)&sOut[r0][4 * dg]      = make_float4(p.x + bA.x, p.y + bA.y, q.x + bA.z, q.y + bA.w);
        p = upk(aB0); q = upk(aB1);
        *(float4*)&sOut[r0][32 + 4 * dg] = make_float4(p.x + bB.x, p.y + bB.y, q.x + bB.z, q.y + bB.w);
        p = upk(bA0); q = upk(bA1);
        *(float4*)&sOut[r1][4 * dg]      = make_float4(p.x + bA.x, p.y + bA.y, q.x + bA.z, q.y + bA.w);
        p = upk(bB0); q = upk(bB1);
        *(float4*)&sOut[r1][32 + 4 * dg] = make_float4(p.x + bB.x, p.y + bB.y, q.x + bB.z, q.y + bB.w);
    }
    __syncthreads();

    // normalize + store PADDED rows: warp w handles rows 8w..8w+7
    int w = tid >> 5, l = tid & 31;
    float* outp = GATHER ? g_tprojn : g_cprojn;
#pragma unroll
    for (int rr = 0; rr < 8; rr++) {
        int r = 8 * w + rr;
        long gr = base + r;
        float v0 = sOut[r][l];
        float v1 = (l < DA - 32) ? sOut[r][l + 32] : 0.f;
        float ss = v0 * v0 + v1 * v1;
#pragma unroll
        for (int o = 16; o >= 1; o >>= 1)
            ss += __shfl_xor_sync(0xffffffffu, ss, o);
        float inv = 1.0f / fmaxf(sqrtf(ss), EPSV);
        if (!GATHER && gr >= VSIZE) continue;
        float* op = outp + gr * DAP;
        op[l] = v0 * inv;
        op[l + 32] = v1 * inv;       // zero for l>=28 -> pads cols 60..63
    }
}

// ---------------------------------------------------------------------------
// Kernel 3: main. One CTA per batch row (R10 dataflow).
// launch_bounds(256,5): cap regs at 51 -> 5 CTAs/SM (occupancy experiment).
// ---------------------------------------------------------------------------
__global__ __launch_bounds__(256, 5)
void main_kernel(const float* __restrict__ cvec,
                 const int* __restrict__ citems,
                 const int* __restrict__ maskp,
                 float* __restrict__ outS)
{
    __shared__ int   s_cit[CN];
    __shared__ int   s_mask[CN];
    __shared__ __align__(16) float s_tp[TN][DAP];
    __shared__ __align__(16) float s_aT[CN][8];            // attn [c][t]
    __shared__ __align__(16) char  arena[8 * 4 * 128 * 8]; // s_cp (27.2K) / s_part (32K ull)
    float (*s_cp)[68] = (float(*)[68])arena;
    ull* sp = (ull*)arena;                                 // [w][tp][e] packed t-pairs

    int b = blockIdx.x;
    int tid = threadIdx.x;
    int w = tid >> 5, l = tid & 31;

    if (tid < CN) {
        s_cit[tid]  = citems[b * CN + tid];
        s_mask[tid] = maskp[b * CN + tid];
    }
    for (int i = tid; i < TN * DAP; i += 256)
        ((float*)s_tp)[i] = g_tprojn[(size_t)b * (TN * DAP) + i];

    // ---- Phase 1: scores; warp w = t, lanes own c-columns ----
    float sc[8];
#pragma unroll
    for (int i = 0; i < 8; i++) sc[i] = -1e30f;

    for (int ch = 0; ch < 2; ch++) {
        __syncthreads();
        int base = ch * CCH;
        for (int r = w; r < CCH; r += 8) {
            int tok = s_cit[base + r];
            if (l < 30) {
                float2 v = ((const float2*)(g_cprojn + (size_t)tok * DAP))[l];
                *(float2*)&s_cp[r][2 * l] = v;
            }
        }
        __syncthreads();

        ull a0 = 0, a1 = 0, a2 = 0, a3 = 0;
#pragma unroll
        for (int d4 = 0; d4 < 15; d4++) {
            ulonglong2 tp = *(const ulonglong2*)&s_tp[w][4 * d4];
            ulonglong2 c0 = *(const ulonglong2*)&s_cp[l][4 * d4];
            a0 = ffma2(c0.x, tp.x, a0); a0 = ffma2(c0.y, tp.y, a0);
            ulonglong2 c1 = *(const ulonglong2*)&s_cp[l + 32][4 * d4];
            a1 = ffma2(c1.x, tp.x, a1); a1 = ffma2(c1.y, tp.y, a1);
            ulonglong2 c2 = *(const ulonglong2*)&s_cp[l + 64][4 * d4];
            a2 = ffma2(c2.x, tp.x, a2); a2 = ffma2(c2.y, tp.y, a2);
            if (l < 4) {
                ulonglong2 c3 = *(const ulonglong2*)&s_cp[l + 96][4 * d4];
                a3 = ffma2(c3.x, tp.x, a3); a3 = ffma2(c3.y, tp.y, a3);
            }
        }
        {
            float2 f;
            f = upk(a0); sc[ch*4+0] = s_mask[base + l]      ? -1e30f : (f.x + f.y);
            f = upk(a1); sc[ch*4+1] = s_mask[base + l + 32] ? -1e30f : (f.x + f.y);
            f = upk(a2); sc[ch*4+2] = s_mask[base + l + 64] ? -1e30f : (f.x + f.y);
            if (l < 4) {
                f = upk(a3); sc[ch*4+3] = s_mask[base + l + 96] ? -1e30f : (f.x + f.y);
            }
        }
    }

    // ---- Phase 2: softmax over c for t=w ----
    {
        float m = sc[0];
#pragma unroll
        for (int i = 1; i < 8; i++) m = fmaxf(m, sc[i]);
#pragma unroll
        for (int o = 16; o >= 1; o >>= 1)
            m = fmaxf(m, __shfl_xor_sync(0xffffffffu, m, o));
        float sum = 0.f;
#pragma unroll
        for (int i = 0; i < 8; i++) { sc[i] = __expf(sc[i] - m); sum += sc[i]; }
#pragma unroll
        for (int o = 16; o >= 1; o >>= 1)
            sum += __shfl_xor_sync(0xffffffffu, sum, o);
        float inv = 1.0f / sum;
#pragma unroll
        for (int i = 0; i < 8; i++) {
            int cl = l + 32 * (i & 3);
            if (cl < CCH) s_aT[(i >> 2) * CCH + cl][w] = sc[i] * inv;
        }
    }
    __syncthreads();   // fences s_cp reads before sp writes

    // ---- Phase 3: partial s over warp's 25-c chunk; lane owns e=4l..4l+3.
    //      Accumulators packed over t-pairs: acc[tp][e] (tp = (2t,2t+1)).
    {
        ull acc[4][4];
#pragma unroll
        for (int i = 0; i < 4; i++)
            acc[i][0] = acc[i][1] = acc[i][2] = acc[i][3] = 0;
        int cbeg = 25 * w;
#pragma unroll 5
        for (int c = cbeg; c < cbeg + 25; c++) {
            int tok = s_cit[c];
            float4 u = *(const float4*)(cvec + (size_t)tok * EDIM + 4 * l);
            ull ud0 = dup2(u.x), ud1 = dup2(u.y), ud2 = dup2(u.z), ud3 = dup2(u.w);
            ulonglong2 A = *(const ulonglong2*)&s_aT[c][0];  // (t0,t1),(t2,t3)
            ulonglong2 B = *(const ulonglong2*)&s_aT[c][4];  // (t4,t5),(t6,t7)
            acc[0][0] = ffma2(A.x, ud0, acc[0][0]);
            acc[0][1] = ffma2(A.x, ud1, acc[0][1]);
            acc[0][2] = ffma2(A.x, ud2, acc[0][2]);
            acc[0][3] = ffma2(A.x, ud3, acc[0][3]);
            acc[1][0] = ffma2(A.y, ud0, acc[1][0]);
            acc[1][1] = ffma2(A.y, ud1, acc[1][1]);
            acc[1][2] = ffma2(A.y, ud2, acc[1][2]);
            acc[1][3] = ffma2(A.y, ud3, acc[1][3]);
            acc[2][0] = ffma2(B.x, ud0, acc[2][0]);
            acc[2][1] = ffma2(B.x, ud1, acc[2][1]);
            acc[2][2] = ffma2(B.x, ud2, acc[2][2]);
            acc[2][3] = ffma2(B.x, ud3, acc[2][3]);
            acc[3][0] = ffma2(B.y, ud0, acc[3][0]);
            acc[3][1] = ffma2(B.y, ud1, acc[3][1]);
            acc[3][2] = ffma2(B.y, ud2, acc[3][2]);
            acc[3][3] = ffma2(B.y, ud3, acc[3][3]);
        }
#pragma unroll
        for (int tp = 0; tp < 4; tp++) {
            ulonglong2 v0; v0.x = acc[tp][0]; v0.y = acc[tp][1];
            ulonglong2 v1; v1.x = acc[tp][2]; v1.y = acc[tp][3];
            *(ulonglong2*)&sp[((size_t)(w * 4 + tp)) * 128 + 4 * l]     = v0;
            *(ulonglong2*)&sp[((size_t)(w * 4 + tp)) * 128 + 4 * l + 2] = v1;
        }
    }
    __syncthreads();

    // ---- reduce 8 warp-partials (packed), write S ----
#pragma unroll
    for (int q = 0; q < 2; q++) {
        int s = tid + 256 * q;            // 0..511 over (tp, e)
        int tp = s >> 7, e = s & 127;
        ull v = sp[(size_t)tp * 128 + e];
#pragma unroll
        for (int p = 1; p < 8; p++)
            v = add2(v, sp[((size_t)(p * 4 + tp)) * 128 + e]);
        float2 f = upk(v);
        float* op = outS + (size_t)b * (TN * EDIM) + (2 * tp) * EDIM + e;
        op[0]    = f.x;
        op[EDIM] = f.y;
    }
}

// ---------------------------------------------------------------------------
// Kernel 4: Z = S @ Mt + bias2  ([32768,128] x [128,128]), 64 rows per CTA.
// ---------------------------------------------------------------------------
__global__ __launch_bounds__(256)
void zgemm_kernel(const float* __restrict__ S, float* __restrict__ outp)
{
    __shared__ __align__(16) float sS[64][128];

    int tid = threadIdx.x;
    int rg = tid >> 4;
    int eg = tid & 15;
    long row0 = (long)blockIdx.x * 64;

    for (int i = tid; i < 64 * 32; i += 256) {
        int r = i >> 5, q = i & 31;
        ((float4*)&sS[r][0])[q] = ((const float4*)(S + (row0 + r) * EDIM))[q];
    }

    ull acc[4][4];
    {
        const ulonglong2* bp = (const ulonglong2*)(g_bias2 + 8 * eg);
        ulonglong2 b0 = bp[0], b1 = bp[1];
#pragma unroll
        for (int j = 0; j < 4; j++) {
            acc[j][0] = b0.x; acc[j][1] = b0.y;
            acc[j][2] = b1.x; acc[j][3] = b1.y;
        }
    }
    __syncthreads();

#pragma unroll 4
    for (int k = 0; k < EDIM; k++) {
        const ulonglong2* mp = (const ulonglong2*)(g_Mt + k * EDIM + 8 * eg);
        ulonglong2 m0 = mp[0], m1 = mp[1];
        ull x0 = dup2(sS[4 * rg + 0][k]);
        ull x1 = dup2(sS[4 * rg + 1][k]);
        ull x2 = dup2(sS[4 * rg + 2][k]);
        ull x3 = dup2(sS[4 * rg + 3][k]);
        acc[0][0] = ffma2(m0.x, x0, acc[0][0]); acc[0][1] = ffma2(m0.y, x0, acc[0][1]);
        acc[0][2] = ffma2(m1.x, x0, acc[0][2]); acc[0][3] = ffma2(m1.y, x0, acc[0][3]);
        acc[1][0] = ffma2(m0.x, x1, acc[1][0]); acc[1][1] = ffma2(m0.y, x1, acc[1][1]);
        acc[1][2] = ffma2(m1.x, x1, acc[1][2]); acc[1][3] = ffma2(m1.y, x1, acc[1][3]);
        acc[2][0] = ffma2(m0.x, x2, acc[2][0]); acc[2][1] = ffma2(m0.y, x2, acc[2][1]);
        acc[2][2] = ffma2(m1.x, x2, acc[2][2]); acc[2][3] = ffma2(m1.y, x2, acc[2][3]);
        acc[3][0] = ffma2(m0.x, x3, acc[3][0]); acc[3][1] = ffma2(m0.y, x3, acc[3][1]);
        acc[3][2] = ffma2(m1.x, x3, acc[3][2]); acc[3][3] = ffma2(m1.y, x3, acc[3][3]);
    }

#pragma unroll
    for (int j = 0; j < 4; j++) {
        float* op = outp + (row0 + 4 * rg + j) * EDIM + 8 * eg;
        float2 f0 = upk(acc[j][0]), f1 = upk(acc[j][1]);
        float2 f2 = upk(acc[j][2]), f3 = upk(acc[j][3]);
        *(float4*)(op)     = make_float4(f0.x, f0.y, f1.x, f1.y);
        *(float4*)(op + 4) = make_float4(f2.x, f2.y, f3.x, f3.y);
    }
}

// ---------------------------------------------------------------------------
extern "C" void kernel_launch(void* const* d_in, const int* in_sizes, int n_in,
                              void* d_out, int out_size)
{
    const float* tvec  = (const float*)d_in[0];
    const float* cvec  = (const float*)d_in[1];
    const float* Ac_w  = (const float*)d_in[2];
    const float* Ac_b  = (const float*)d_in[3];
    const float* At_w  = (const float*)d_in[4];
    const float* At_b  = (const float*)d_in[5];
    const float* Bc_w  = (const float*)d_in[6];
    const float* Bc_b  = (const float*)d_in[7];
    const float* R_w   = (const float*)d_in[8];
    const float* R_b   = (const float*)d_in[9];
    const int*   titems = (const int*)d_in[10];
    const int*   citems = (const int*)d_in[11];
    const int*   maskp  = (const int*)d_in[12];

    float* S;
    cudaGetSymbolAddress((void**)&S, g_S);

    fuse_kernel<<<EDIM, EDIM>>>(R_w, Bc_w, Bc_b, R_b);
    proj_kernel<false><<<(VSIZE + 63) / 64, 256>>>(cvec, Ac_w, Ac_b, nullptr);
    proj_kernel<true><<<(BN * TN) / 64, 256>>>(tvec, At_w, At_b, titems);
    main_kernel<<<BN, 256>>>(cvec, citems, maskp, S);
    zgemm_kernel<<<(BN * TN) / 64, 256>>>(S, (float*)d_out);
}

// round 17
// speedup vs baseline: 1.0872x; 1.0594x over previous
#include <cuda_runtime.h>
#include <cstdint>

#define VSIZE 100000
#define EDIM  128
#define DA    60
#define DAP   64            // padded projection row (256B aligned)
#define BN    4096
#define TN    8
#define CN    200
#define EPSV  1e-6f
#define CCH   100

typedef unsigned long long ull;

// Scratch (device globals: no allocation allowed)
__device__ float g_cprojn[(size_t)VSIZE * DAP];    // normalized c projections [V,64p]
__device__ float g_tprojn[(size_t)BN * TN * DAP];  // normalized t projections [B*T,64p]
__device__ float g_Mt[EDIM * EDIM];                // Mt[k][e] = (R_w @ Bc_w)[e][k]
__device__ float g_bias2[EDIM];                    // R_w @ Bc_b + R_b

// ---------------------------------------------------------------------------
// packed fp32x2 helpers
// ---------------------------------------------------------------------------
__device__ __forceinline__ ull ffma2(ull a, ull b, ull c) {
    ull d; asm("fma.rn.f32x2 %0,%1,%2,%3;" : "=l"(d) : "l"(a), "l"(b), "l"(c));
    return d;
}
__device__ __forceinline__ ull add2(ull a, ull b) {
    ull d; asm("add.rn.f32x2 %0,%1,%2;" : "=l"(d) : "l"(a), "l"(b));
    return d;
}
__device__ __forceinline__ ull dup2(float x) {
    ull r; asm("mov.b64 %0,{%1,%1};" : "=l"(r) : "f"(x)); return r;
}
__device__ __forceinline__ float2 upk(ull v) {
    float a, b; asm("mov.b64 {%0,%1},%2;" : "=f"(a), "=f"(b) : "l"(v));
    return make_float2(a, b);
}

// ---------------------------------------------------------------------------
// Kernel 0: fuse M = R_w @ Bc_w (stored transposed) and bias2 = R_w@Bc_b + R_b
// ---------------------------------------------------------------------------
__global__ void fuse_kernel(const float* __restrict__ Rw, const float* __restrict__ Bw,
                            const float* __restrict__ Bb, const float* __restrict__ Rb)
{
    int e = blockIdx.x;
    int k = threadIdx.x;
    __shared__ float sR[EDIM];
    __shared__ float sP[EDIM];
    sR[k] = Rw[e * EDIM + k];
    __syncthreads();
    float acc = 0.f;
#pragma unroll 8
    for (int j = 0; j < EDIM; j++)
        acc = fmaf(sR[j], Bw[j * EDIM + k], acc);
    g_Mt[k * EDIM + e] = acc;
    sP[k] = sR[k] * Bb[k];
    __syncthreads();
    if (k == 0) {
        float s = 0.f;
        for (int j = 0; j < EDIM; j++) s += sP[j];
        g_bias2[e] = s + Rb[e];
    }
}

// ---------------------------------------------------------------------------
// Kernel 1/2: project 64 rows/CTA through W[60,128]+bias, eps-clamped L2 norm.
// (R10 version — proven fastest proj.)
// Writes PADDED rows (DAP=64 floats; cols 60..63 = 0).
// ---------------------------------------------------------------------------
template <bool GATHER>
__global__ __launch_bounds__(256)
void proj_kernel(const float* __restrict__ table,
                 const float* __restrict__ W,
                 const float* __restrict__ bias,
                 const int* __restrict__ idx)
{
    __shared__ __align__(16) float sWt[64][68];
    __shared__ __align__(16) char  arena[64 * 68 * 4];
    float (*sX)[68]   = (float(*)[68])arena;
    float (*sOut)[68] = (float(*)[68])arena;

    int tid = threadIdx.x;
    int rg = tid >> 3, dg = tid & 7;
    int r0 = 2 * rg, r1 = r0 + 1;
    long base = (long)blockIdx.x * 64;

    ull aA0 = 0, aA1 = 0, aB0 = 0, aB1 = 0;
    ull bA0 = 0, bA1 = 0, bB0 = 0, bB1 = 0;

#pragma unroll
    for (int h = 0; h < 2; h++) {
        __syncthreads();
        for (int i = tid; i < DA * 64; i += 256) {
            int d = i >> 6, kk = i & 63;
            sWt[kk][d] = W[d * EDIM + 64 * h + kk];
        }
        for (int i = tid; i < 64 * 4; i += 256)
            sWt[i >> 2][60 + (i & 3)] = 0.f;
        for (int i = tid; i < 64 * 16; i += 256) {
            int r = i >> 4, q = i & 15;
            long gr = base + r;
            long rv = GATHER ? (long)idx[gr] : (gr < VSIZE ? gr : (long)(VSIZE - 1));
            ((float4*)&sX[r][0])[q] =
                ((const float4*)(table + rv * EDIM + 64 * h))[q];
        }
        __syncthreads();

#pragma unroll 8
        for (int k = 0; k < 64; k++) {
            ulonglong2 wA = *(const ulonglong2*)&sWt[k][4 * dg];
            ulonglong2 wB = *(const ulonglong2*)&sWt[k][32 + 4 * dg];
            ull x0 = dup2(sX[r0][k]);
            ull x1 = dup2(sX[r1][k]);
            aA0 = ffma2(wA.x, x0, aA0); aA1 = ffma2(wA.y, x0, aA1);
            aB0 = ffma2(wB.x, x0, aB0); aB1 = ffma2(wB.y, x0, aB1);
            bA0 = ffma2(wA.x, x1, bA0); bA1 = ffma2(wA.y, x1, bA1);
            bB0 = ffma2(wB.x, x1, bB0); bB1 = ffma2(wB.y, x1, bB1);
        }
    }
    __syncthreads();

    {
        float4 bA = *(const float4*)(bias + 4 * dg);
        float4 bB;
        if (32 + 4 * dg < DA) bB = *(const float4*)(bias + 32 + 4 * dg);
        else                  bB = make_float4(0.f, 0.f, 0.f, 0.f);
        float2 p, q;
        p = upk(aA0); q = upk(aA1);
        *(float4*)&sOut[r0][4 * dg]      = make_float4(p.x + bA.x, p.y + bA.y, q.x + bA.z, q.y + bA.w);
        p = upk(aB0); q = upk(aB1);
        *(float4*)&sOut[r0][32 + 4 * dg] = make_float4(p.x + bB.x, p.y + bB.y, q.x + bB.z, q.y + bB.w);
        p = upk(bA0); q = upk(bA1);
        *(float4*)&sOut[r1][4 * dg]      = make_float4(p.x + bA.x, p.y + bA.y, q.x + bA.z, q.y + bA.w);
        p = upk(bB0); q = upk(bB1);
        *(float4*)&sOut[r1][32 + 4 * dg] = make_float4(p.x + bB.x, p.y + bB.y, q.x + bB.z, q.y + bB.w);
    }
    __syncthreads();

    // normalize + store PADDED rows: warp w handles rows 8w..8w+7
    int w = tid >> 5, l = tid & 31;
    float* outp = GATHER ? g_tprojn : g_cprojn;
#pragma unroll
    for (int rr = 0; rr < 8; rr++) {
        int r = 8 * w + rr;
        long gr = base + r;
        float v0 = sOut[r][l];
        float v1 = (l < DA - 32) ? sOut[r][l + 32] : 0.f;
        float ss = v0 * v0 + v1 * v1;
#pragma unroll
        for (int o = 16; o >= 1; o >>= 1)
            ss += __shfl_xor_sync(0xffffffffu, ss, o);
        float inv = 1.0f / fmaxf(sqrtf(ss), EPSV);
        if (!GATHER && gr >= VSIZE) continue;
        float* op = outp + gr * DAP;
        op[l] = v0 * inv;
        op[l + 32] = v1 * inv;       // zero for l>=28 -> pads cols 60..63
    }
}

// ---------------------------------------------------------------------------
// Kernel 3: main. One CTA per batch row. P1-P4 fused. No smem overlays between
// different element types: s_aT stays float for its whole life; the reduced s
// (sp2, [k][4] ull) is written into the FRONT of the arena after sp is dead,
// with a register-held handoff across a barrier.
// ---------------------------------------------------------------------------
__global__ __launch_bounds__(256, 4)
void main_kernel(const float* __restrict__ cvec,
                 const int* __restrict__ citems,
                 const int* __restrict__ maskp,
                 float* __restrict__ outp)
{
    __shared__ int   s_cit[CN];
    __shared__ int   s_mask[CN];
    __shared__ __align__(16) float s_tp[TN][DAP];
    __shared__ __align__(16) float s_aT[CN][8];            // attn [c][t]
    __shared__ __align__(16) char  arena[8 * 4 * 128 * 8]; // s_cp / sp / sp2
    float (*s_cp)[68] = (float(*)[68])arena;
    ull* sp = (ull*)arena;                                 // [w*4+tp][e] packed t-pairs
    ull (*sp2)[4] = (ull(*)[4])arena;                      // [k][tp] after sp dies

    int b = blockIdx.x;
    int tid = threadIdx.x;
    int w = tid >> 5, l = tid & 31;

    if (tid < CN) {
        s_cit[tid]  = citems[b * CN + tid];
        s_mask[tid] = maskp[b * CN + tid];
    }
    for (int i = tid; i < TN * DAP; i += 256)
        ((float*)s_tp)[i] = g_tprojn[(size_t)b * (TN * DAP) + i];

    // ---- Phase 1: scores; warp w = t, lanes own c-columns ----
    float sc[8];
#pragma unroll
    for (int i = 0; i < 8; i++) sc[i] = -1e30f;

    for (int ch = 0; ch < 2; ch++) {
        __syncthreads();
        int base = ch * CCH;
        for (int r = w; r < CCH; r += 8) {
            int tok = s_cit[base + r];
            if (l < 30) {
                float2 v = ((const float2*)(g_cprojn + (size_t)tok * DAP))[l];
                *(float2*)&s_cp[r][2 * l] = v;
            }
        }
        __syncthreads();

        ull a0 = 0, a1 = 0, a2 = 0, a3 = 0;
#pragma unroll
        for (int d4 = 0; d4 < 15; d4++) {
            ulonglong2 tp = *(const ulonglong2*)&s_tp[w][4 * d4];
            ulonglong2 c0 = *(const ulonglong2*)&s_cp[l][4 * d4];
            a0 = ffma2(c0.x, tp.x, a0); a0 = ffma2(c0.y, tp.y, a0);
            ulonglong2 c1 = *(const ulonglong2*)&s_cp[l + 32][4 * d4];
            a1 = ffma2(c1.x, tp.x, a1); a1 = ffma2(c1.y, tp.y, a1);
            ulonglong2 c2 = *(const ulonglong2*)&s_cp[l + 64][4 * d4];
            a2 = ffma2(c2.x, tp.x, a2); a2 = ffma2(c2.y, tp.y, a2);
            if (l < 4) {
                ulonglong2 c3 = *(const ulonglong2*)&s_cp[l + 96][4 * d4];
                a3 = ffma2(c3.x, tp.x, a3); a3 = ffma2(c3.y, tp.y, a3);
            }
        }
        {
            float2 f;
            f = upk(a0); sc[ch*4+0] = s_mask[base + l]      ? -1e30f : (f.x + f.y);
            f = upk(a1); sc[ch*4+1] = s_mask[base + l + 32] ? -1e30f : (f.x + f.y);
            f = upk(a2); sc[ch*4+2] = s_mask[base + l + 64] ? -1e30f : (f.x + f.y);
            if (l < 4) {
                f = upk(a3); sc[ch*4+3] = s_mask[base + l + 96] ? -1e30f : (f.x + f.y);
            }
        }
    }

    // ---- Phase 2: softmax over c for t=w ----
    {
        float m = sc[0];
#pragma unroll
        for (int i = 1; i < 8; i++) m = fmaxf(m, sc[i]);
#pragma unroll
        for (int o = 16; o >= 1; o >>= 1)
            m = fmaxf(m, __shfl_xor_sync(0xffffffffu, m, o));
        float sum = 0.f;
#pragma unroll
        for (int i = 0; i < 8; i++) { sc[i] = __expf(sc[i] - m); sum += sc[i]; }
#pragma unroll
        for (int o = 16; o >= 1; o >>= 1)
            sum += __shfl_xor_sync(0xffffffffu, sum, o);
        float inv = 1.0f / sum;
#pragma unroll
        for (int i = 0; i < 8; i++) {
            int cl = l + 32 * (i & 3);
            if (cl < CCH) s_aT[(i >> 2) * CCH + cl][w] = sc[i] * inv;
        }
    }
    __syncthreads();   // fences s_cp reads before sp writes

    // ---- Phase 3: partial s over warp's 25-c chunk; lane owns e=4l..4l+3.
    //      Accumulators packed over t-pairs: acc[tp][e] (tp = (2t,2t+1)).
    {
        ull acc[4][4];
#pragma unroll
        for (int i = 0; i < 4; i++)
            acc[i][0] = acc[i][1] = acc[i][2] = acc[i][3] = 0;
        int cbeg = 25 * w;
#pragma unroll 5
        for (int c = cbeg; c < cbeg + 25; c++) {
            int tok = s_cit[c];
            float4 u = *(const float4*)(cvec + (size_t)tok * EDIM + 4 * l);
            ull ud0 = dup2(u.x), ud1 = dup2(u.y), ud2 = dup2(u.z), ud3 = dup2(u.w);
            ulonglong2 A = *(const ulonglong2*)&s_aT[c][0];  // (t0,t1),(t2,t3)
            ulonglong2 B = *(const ulonglong2*)&s_aT[c][4];  // (t4,t5),(t6,t7)
            acc[0][0] = ffma2(A.x, ud0, acc[0][0]);
            acc[0][1] = ffma2(A.x, ud1, acc[0][1]);
            acc[0][2] = ffma2(A.x, ud2, acc[0][2]);
            acc[0][3] = ffma2(A.x, ud3, acc[0][3]);
            acc[1][0] = ffma2(A.y, ud0, acc[1][0]);
            acc[1][1] = ffma2(A.y, ud1, acc[1][1]);
            acc[1][2] = ffma2(A.y, ud2, acc[1][2]);
            acc[1][3] = ffma2(A.y, ud3, acc[1][3]);
            acc[2][0] = ffma2(B.x, ud0, acc[2][0]);
            acc[2][1] = ffma2(B.x, ud1, acc[2][1]);
            acc[2][2] = ffma2(B.x, ud2, acc[2][2]);
            acc[2][3] = ffma2(B.x, ud3, acc[2][3]);
            acc[3][0] = ffma2(B.y, ud0, acc[3][0]);
            acc[3][1] = ffma2(B.y, ud1, acc[3][1]);
            acc[3][2] = ffma2(B.y, ud2, acc[3][2]);
            acc[3][3] = ffma2(B.y, ud3, acc[3][3]);
        }
#pragma unroll
        for (int tp = 0; tp < 4; tp++) {
            ulonglong2 v0; v0.x = acc[tp][0]; v0.y = acc[tp][1];
            ulonglong2 v1; v1.x = acc[tp][2]; v1.y = acc[tp][3];
            *(ulonglong2*)&sp[((size_t)(w * 4 + tp)) * 128 + 4 * l]     = v0;
            *(ulonglong2*)&sp[((size_t)(w * 4 + tp)) * 128 + 4 * l + 2] = v1;
        }
    }
    __syncthreads();   // sp complete

    // ---- reduce 8 warp-partials into registers, then place sp2 at arena front ----
    {
        ull red[2];
#pragma unroll
        for (int q = 0; q < 2; q++) {
            int s = tid + 256 * q;            // 0..511 over (tp, k)
            int tp = s >> 7, k = s & 127;
            ull v = sp[(size_t)tp * 128 + k];
#pragma unroll
            for (int p = 1; p < 8; p++)
                v = add2(v, sp[((size_t)(p * 4 + tp)) * 128 + k]);
            red[q] = v;
        }
        __syncthreads();   // all sp reads done; arena reusable as sp2
#pragma unroll
        for (int q = 0; q < 2; q++) {
            int s = tid + 256 * q;
            int tp = s >> 7, k = s & 127;
            sp2[k][tp] = red[q];
        }
    }
    __syncthreads();

    // ---- Phase 4 (inline): z[t][e] = sum_k s[t][k]*Mt[k][e] + bias2[e] ----
    {
        int e = tid & 127, th = tid >> 7;    // th selects tp-pair (0,1) or (2,3)
        int tp0 = 2 * th;
        ull z0 = 0, z1 = 0;
#pragma unroll 4
        for (int k = 0; k < EDIM; k++) {
            ull md = dup2(g_Mt[k * EDIM + e]);
            ulonglong2 sv = *(const ulonglong2*)&sp2[k][tp0];  // 16B-aligned
            z0 = ffma2(sv.x, md, z0);
            z1 = ffma2(sv.y, md, z1);
        }
        float be = g_bias2[e];
        float2 f0 = upk(z0), f1 = upk(z1);
        float* op = outp + (size_t)b * (TN * EDIM) + e;
        op[(2 * tp0 + 0) * EDIM] = f0.x + be;
        op[(2 * tp0 + 1) * EDIM] = f0.y + be;
        op[(2 * tp0 + 2) * EDIM] = f1.x + be;
        op[(2 * tp0 + 3) * EDIM] = f1.y + be;
    }
}

// ---------------------------------------------------------------------------
extern "C" void kernel_launch(void* const* d_in, const int* in_sizes, int n_in,
                              void* d_out, int out_size)
{
    const float* tvec  = (const float*)d_in[0];
    const float* cvec  = (const float*)d_in[1];
    const float* Ac_w  = (const float*)d_in[2];
    const float* Ac_b  = (const float*)d_in[3];
    const float* At_w  = (const float*)d_in[4];
    const float* At_b  = (const float*)d_in[5];
    const float* Bc_w  = (const float*)d_in[6];
    const float* Bc_b  = (const float*)d_in[7];
    const float* R_w   = (const float*)d_in[8];
    const float* R_b   = (const float*)d_in[9];
    const int*   titems = (const int*)d_in[10];
    const int*   citems = (const int*)d_in[11];
    const int*   maskp  = (const int*)d_in[12];

    fuse_kernel<<<EDIM, EDIM>>>(R_w, Bc_w, Bc_b, R_b);
    proj_kernel<false><<<(VSIZE + 63) / 64, 256>>>(cvec, Ac_w, Ac_b, nullptr);
    proj_kernel<true><<<(BN * TN) / 64, 256>>>(tvec, At_w, At_b, titems);
    main_kernel<<<BN, 256>>>(cvec, citems, maskp, (float*)d_out);
}